// round 16
// baseline (speedup 1.0000x reference)
#include <cuda_runtime.h>
#include <cuda_bf16.h>
#include <cstdint>

#define NB 8
#define PTS 4096
#define NPT 32768
#define DD 256
#define QT_N 3000
#define QR_N 216
#define PQ 3456
#define SROW 264
#define MROW 72
#define SCALE 0.0625f

// ---------------- device scratch ----------------
__device__ float          g_wv[3][DD];
__device__ float          g_vsum[3][NPT];
__device__ __nv_bfloat16  g_featTs[(size_t)4*DD*NPT];   // [var][d][n], n contiguous (64MB)
__device__ __nv_bfloat16  g_qeff[(size_t)PQ*DD];
__device__ float          g_qeff32[(size_t)PQ*DD];
__device__ float          g_F1[NB][DD];
__device__ float          g_Wv1[NB][3][DD];
__device__ float          g_base[NB][3];
__device__ float          g_momp[(size_t)512*16384];    // Gram partials (32MB)
__device__ __nv_bfloat16  g_gram[(size_t)32*65536];     // [b*4+var][256][256] bf16
__device__ float          g_quad[(size_t)NB*PQ*2];

struct TileInfo { int head, rowbase, valid; };
__device__ __forceinline__ TileInfo tile_info(int st) {
    TileInfo ti;
    if (st < 48)      { ti.head = 0; ti.rowbase = st*64;      ti.valid = max(0, min(64, QT_N - ti.rowbase)); }
    else if (st < 52) { ti.head = 1; ti.rowbase = (st-48)*64; ti.valid = max(0, min(64, QR_N - ti.rowbase)); }
    else              { ti.head = 2; ti.rowbase = 0;          ti.valid = (st == 52) ? 1 : 0; }
    return ti;
}

// ---------------- helpers ----------------
__device__ __forceinline__ uint32_t sptr(const void* p) {
    return (uint32_t)__cvta_generic_to_shared(p);
}
__device__ __forceinline__ void ldsm4(uint32_t* r, uint32_t a) {
    asm volatile("ldmatrix.sync.aligned.m8n8.x4.shared.b16 {%0,%1,%2,%3},[%4];"
                 : "=r"(r[0]), "=r"(r[1]), "=r"(r[2]), "=r"(r[3]) : "r"(a));
}
__device__ __forceinline__ void mma16816(float* c, const uint32_t* a, uint32_t b0, uint32_t b1) {
    asm volatile("mma.sync.aligned.m16n8k16.row.col.f32.bf16.bf16.f32 "
                 "{%0,%1,%2,%3},{%4,%5,%6,%7},{%8,%9},{%0,%1,%2,%3};"
                 : "+f"(c[0]), "+f"(c[1]), "+f"(c[2]), "+f"(c[3])
                 : "r"(a[0]), "r"(a[1]), "r"(a[2]), "r"(a[3]), "r"(b0), "r"(b1));
}
__device__ __forceinline__ void mma16816z(float* c, const uint32_t* a, uint32_t b0, uint32_t b1) {
    asm volatile("mma.sync.aligned.m16n8k16.row.col.f32.bf16.bf16.f32 "
                 "{%0,%1,%2,%3},{%4,%5,%6,%7},{%8,%9},{%10,%10,%10,%10};"
                 : "=f"(c[0]), "=f"(c[1]), "=f"(c[2]), "=f"(c[3])
                 : "r"(a[0]), "r"(a[1]), "r"(a[2]), "r"(a[3]), "r"(b0), "r"(b1), "f"(0.f));
}
__device__ __forceinline__ void cpa16(uint32_t dst, const void* src) {
    asm volatile("cp.async.cg.shared.global [%0],[%1],16;" :: "r"(dst), "l"(src) : "memory");
}
__device__ __forceinline__ void cpa_commit() { asm volatile("cp.async.commit_group;" ::: "memory"); }
template<int N> __device__ __forceinline__ void cpa_wait() {
    asm volatile("cp.async.wait_group %0;" :: "n"(N) : "memory");
}
// stage 128x256 bf16 tile (gsrc row stride 256) into smem stride SROW
__device__ __forceinline__ void load_tile(uint32_t sdst, const __nv_bfloat16* gsrc, int tid) {
    #pragma unroll
    for (int i = 0; i < 16; i++) {
        int idx = tid + i*256;
        int r = idx >> 5, c = idx & 31;
        cpa16(sdst + (uint32_t)(r*SROW + c*8)*2, gsrc + r*DD + c*8);
    }
}

// ---------------- K1: wv[h][c] = sum_d Wv_h[c][d] ----------------
__global__ void k_wv(const float* __restrict__ WvT, const float* __restrict__ WvR,
                     const float* __restrict__ WvO) {
    int h  = blockIdx.x >> 3;
    int cg = blockIdx.x & 7;
    const float* W = (h == 0) ? WvT : (h == 1) ? WvR : WvO;
    int w = threadIdx.x >> 5, lane = threadIdx.x & 31;
    #pragma unroll
    for (int i = 0; i < 4; i++) {
        int c = cg*32 + w*4 + i;
        const float* row = W + c*DD;
        float s = 0.f;
        #pragma unroll
        for (int j = 0; j < 8; j++) s += row[lane + j*32];
        #pragma unroll
        for (int o = 16; o > 0; o >>= 1) s += __shfl_xor_sync(0xffffffffu, s, o);
        if (lane == 0) g_wv[h][c] = s;
    }
}

// ---------------- K2: v + transposed bf16 feat (raw + 3 v-scaled variants) ----------------
__global__ void __launch_bounds__(256) k_vsum(const float* __restrict__ feat) {
    extern __shared__ unsigned char svm[];
    __nv_bfloat16* tile = (__nv_bfloat16*)svm;      // [128][260]
    float* sv = (float*)(svm + 128*260*2);          // [3][128]
    int gbase = blockIdx.x * 128;
    int tid = threadIdx.x, w = tid >> 5, lane = tid & 31;
    int d0 = lane*4;
    for (int it = 0; it < 16; it++) {
        int pt = w*16 + it;
        const float4* row4 = (const float4*)(feat + (size_t)(gbase + pt)*DD);
        float4 a = row4[lane], bq = row4[lane + 32];
        float f[8] = {a.x, a.y, a.z, a.w, bq.x, bq.y, bq.z, bq.w};
        float s0 = 0.f, s1 = 0.f, s2 = 0.f;
        #pragma unroll
        for (int i = 0; i < 4; i++) {
            s0 += f[i]*g_wv[0][d0+i] + f[4+i]*g_wv[0][128+d0+i];
            s1 += f[i]*g_wv[1][d0+i] + f[4+i]*g_wv[1][128+d0+i];
            s2 += f[i]*g_wv[2][d0+i] + f[4+i]*g_wv[2][128+d0+i];
        }
        #pragma unroll
        for (int o = 16; o > 0; o >>= 1) {
            s0 += __shfl_xor_sync(0xffffffffu, s0, o);
            s1 += __shfl_xor_sync(0xffffffffu, s1, o);
            s2 += __shfl_xor_sync(0xffffffffu, s2, o);
        }
        union { uint2 u; __nv_bfloat16 h[4]; } p0, p1;
        #pragma unroll
        for (int i = 0; i < 4; i++) { p0.h[i] = __float2bfloat16(f[i]); p1.h[i] = __float2bfloat16(f[4+i]); }
        *(uint2*)(tile + pt*260 + d0)       = p0.u;
        *(uint2*)(tile + pt*260 + 128 + d0) = p1.u;
        if (lane == 0) {
            sv[pt] = s0; sv[128 + pt] = s1; sv[256 + pt] = s2;
            g_vsum[0][gbase + pt] = s0; g_vsum[1][gbase + pt] = s1; g_vsum[2][gbase + pt] = s2;
        }
    }
    __syncthreads();
    // phase2: 1024 (var,d) rows over 8 warps; coalesced bf16 stores
    for (int row = w; row < 1024; row += 8) {
        int var = row >> 8, d = row & 255;
        size_t dst = (size_t)row*NPT + gbase + lane;
        #pragma unroll
        for (int j = 0; j < 4; j++) {
            int p = lane + 32*j;
            __nv_bfloat16 rv = tile[p*260 + d];
            __nv_bfloat16 ov = (var == 0) ? rv
                : __float2bfloat16(__bfloat162float(rv) * sv[(var-1)*128 + p]);
            g_featTs[dst + 32*j] = ov;
        }
    }
}

// ---------------- K2b: first moments (exact fp32) ----------------
__global__ void __launch_bounds__(256) k_mom1() {
    int b = blockIdx.x >> 3, dseg = blockIdx.x & 7;
    int w = threadIdx.x >> 5, lane = threadIdx.x & 31;
    #pragma unroll 1
    for (int i = 0; i < 4; i++) {
        int d = dseg*32 + w*4 + i;
        const __nv_bfloat16* fr = g_featTs + (size_t)d*NPT + b*PTS;
        const float* v0 = g_vsum[0] + b*PTS;
        const float* v1 = g_vsum[1] + b*PTS;
        const float* v2 = g_vsum[2] + b*PTS;
        float fs = 0.f, w0 = 0.f, w1 = 0.f, w2 = 0.f;
        for (int c = 0; c < 16; c++) {
            int n0 = lane*8 + c*256;
            uint4 u = *(const uint4*)(fr + n0);
            const __nv_bfloat16* hb = (const __nv_bfloat16*)&u;
            float4 va = *(const float4*)(v0 + n0), vb = *(const float4*)(v0 + n0 + 4);
            float4 wa = *(const float4*)(v1 + n0), wb = *(const float4*)(v1 + n0 + 4);
            float4 xa = *(const float4*)(v2 + n0), xb = *(const float4*)(v2 + n0 + 4);
            float fv[8];
            #pragma unroll
            for (int k = 0; k < 8; k++) { fv[k] = __bfloat162float(hb[k]); fs += fv[k]; }
            w0 += fv[0]*va.x + fv[1]*va.y + fv[2]*va.z + fv[3]*va.w
                + fv[4]*vb.x + fv[5]*vb.y + fv[6]*vb.z + fv[7]*vb.w;
            w1 += fv[0]*wa.x + fv[1]*wa.y + fv[2]*wa.z + fv[3]*wa.w
                + fv[4]*wb.x + fv[5]*wb.y + fv[6]*wb.z + fv[7]*wb.w;
            w2 += fv[0]*xa.x + fv[1]*xa.y + fv[2]*xa.z + fv[3]*xa.w
                + fv[4]*xb.x + fv[5]*xb.y + fv[6]*xb.z + fv[7]*xb.w;
        }
        #pragma unroll
        for (int o = 16; o > 0; o >>= 1) {
            fs += __shfl_xor_sync(0xffffffffu, fs, o);
            w0 += __shfl_xor_sync(0xffffffffu, w0, o);
            w1 += __shfl_xor_sync(0xffffffffu, w1, o);
            w2 += __shfl_xor_sync(0xffffffffu, w2, o);
        }
        if (lane == 0) {
            g_F1[b][d] = fs;
            g_Wv1[b][0][d] = w0; g_Wv1[b][1][d] = w1; g_Wv1[b][2][d] = w2;
        }
    }
    if (dseg == 0 && w < 3) {
        float s = 0.f;
        for (int j = 0; j < 32; j++) {
            float4 v = *(const float4*)(g_vsum[w] + b*PTS + j*128 + lane*4);
            s += v.x + v.y + v.z + v.w;
        }
        #pragma unroll
        for (int o = 16; o > 0; o >>= 1) s += __shfl_xor_sync(0xffffffffu, s, o);
        if (lane == 0) g_base[b][w] = s;
    }
}

// ---------------- K3: Qeff bf16 + fp32 ----------------
__device__ __forceinline__ void gemm64(const __nv_bfloat16* sa, const __nv_bfloat16* sb,
                                       float acc[2][2][4], int wm, int wn, int lane) {
    int arow = lane & 15, acol = (lane >> 4) << 3;
    uint32_t abase0 = sptr(sa + (wm*32 + arow)*SROW + acol);
    uint32_t abase1 = abase0 + 16*SROW*2;
    int brow = ((lane >> 4) & 1)*8 + (lane & 7);
    int bcol = ((lane >> 3) & 1) << 3;
    uint32_t bbase = sptr(sb + (wn*16 + brow)*SROW + bcol);
    #pragma unroll
    for (int k0 = 0; k0 < DD; k0 += 16) {
        uint32_t A0[4], A1[4], Bv[4];
        ldsm4(A0, abase0 + k0*2);
        ldsm4(A1, abase1 + k0*2);
        ldsm4(Bv, bbase  + k0*2);
        mma16816(acc[0][0], A0, Bv[0], Bv[1]);
        mma16816(acc[0][1], A0, Bv[2], Bv[3]);
        mma16816(acc[1][0], A1, Bv[0], Bv[1]);
        mma16816(acc[1][1], A1, Bv[2], Bv[3]);
    }
}

__global__ void __launch_bounds__(256) k_qeff(const float* __restrict__ qTp, const float* __restrict__ WkT,
                                              const float* __restrict__ qRp, const float* __restrict__ WkR,
                                              const float* __restrict__ qOp, const float* __restrict__ WkO) {
    extern __shared__ __nv_bfloat16 sm3[];
    __nv_bfloat16* sa = sm3;
    __nv_bfloat16* sb = sm3 + 64*SROW;
    int st = blockIdx.x, ct = blockIdx.y;
    TileInfo ti = tile_info(st);
    const float* Q  = (ti.head == 0) ? qTp : (ti.head == 1) ? qRp : qOp;
    const float* Wk = (ti.head == 0) ? WkT : (ti.head == 1) ? WkR : WkO;
    int tid = threadIdx.x;
    #pragma unroll 4
    for (int i = tid; i < 64*64; i += 256) {
        int r = i >> 6, c4 = (i & 63) << 2;
        float4 qv = make_float4(0.f, 0.f, 0.f, 0.f);
        if (r < ti.valid) qv = *(const float4*)(Q + (size_t)(ti.rowbase + r)*DD + c4);
        float4 wv = *(const float4*)(Wk + (size_t)(ct*64 + r)*DD + c4);
        union { uint2 u; __nv_bfloat16 b[4]; } pq, pw;
        pq.b[0] = __float2bfloat16(qv.x); pq.b[1] = __float2bfloat16(qv.y);
        pq.b[2] = __float2bfloat16(qv.z); pq.b[3] = __float2bfloat16(qv.w);
        pw.b[0] = __float2bfloat16(wv.x); pw.b[1] = __float2bfloat16(wv.y);
        pw.b[2] = __float2bfloat16(wv.z); pw.b[3] = __float2bfloat16(wv.w);
        *(uint2*)(sa + r*SROW + c4) = pq.u;
        *(uint2*)(sb + r*SROW + c4) = pw.u;
    }
    __syncthreads();
    int lane = tid & 31, w = tid >> 5, wm = w >> 2, wn = w & 3;
    float acc[2][2][4];
    #pragma unroll
    for (int a = 0; a < 2; a++)
        #pragma unroll
        for (int b2 = 0; b2 < 2; b2++)
            #pragma unroll
            for (int c = 0; c < 4; c++) acc[a][b2][c] = 0.f;
    gemm64(sa, sb, acc, wm, wn, lane);
    int g2 = lane >> 2, t = lane & 3;
    #pragma unroll
    for (int mi = 0; mi < 2; mi++)
        #pragma unroll
        for (int nj = 0; nj < 2; nj++) {
            int cc = ct*64 + wn*16 + nj*8 + 2*t;
            int p0 = st*64 + wm*32 + mi*16 + g2;
            float v0 = acc[mi][nj][0]*SCALE, v1 = acc[mi][nj][1]*SCALE;
            float v2 = acc[mi][nj][2]*SCALE, v3 = acc[mi][nj][3]*SCALE;
            __nv_bfloat162 lo, hi;
            lo.x = __float2bfloat16(v0); lo.y = __float2bfloat16(v1);
            hi.x = __float2bfloat16(v2); hi.y = __float2bfloat16(v3);
            *(__nv_bfloat162*)(g_qeff + (size_t)p0*DD + cc)     = lo;
            *(__nv_bfloat162*)(g_qeff + (size_t)(p0+8)*DD + cc) = hi;
            *(float2*)(g_qeff32 + (size_t)p0*DD + cc)     = make_float2(v0, v1);
            *(float2*)(g_qeff32 + (size_t)(p0+8)*DD + cc) = make_float2(v2, v3);
        }
}

// ---------------- K4: Gram tiles (A = raw featT, B = variant featT) ----------------
#define MA_OFF(s) ((uint32_t)(s)*18432u)
#define MB_OFF(s) (36864u + (uint32_t)(s)*18432u)
#define SMEM_MOM  73728

__global__ void __launch_bounds__(256, 1) k_mom() {
    extern __shared__ unsigned char sm[];
    uint32_t smb = sptr(sm);
    int tile = blockIdx.x, ks = blockIdx.y, bv = blockIdx.z;
    int tm = tile >> 1, tn = tile & 1, b = bv >> 2, var = bv & 3;
    int tid = threadIdx.x, lane = tid & 31, wid = tid >> 5;
    int wm = wid >> 2, wn = wid & 3;
    size_t Abase = (size_t)(tm*128)*NPT + b*PTS + ks*1024;
    size_t Bbase = (size_t)(var*256 + tn*128)*NPT + b*PTS + ks*1024;
    auto stage = [&](uint32_t soff, size_t gb, int ch) {
        #pragma unroll
        for (int t = 0; t < 4; t++) {
            int idx = tid + t*256, r = idx >> 3, c = idx & 7;   // 128 rows x 8 x 16B
            cpa16(smb + soff + (uint32_t)(r*MROW + c*8)*2,
                  g_featTs + gb + (size_t)r*NPT + ch*64 + c*8);
        }
    };
    stage(MA_OFF(0), Abase, 0); stage(MB_OFF(0), Bbase, 0); cpa_commit();
    float acc[4][4][4];
    uint32_t aoff = (uint32_t)((wm*64 + (lane & 15))*MROW + ((lane >> 4) << 3))*2;
    int brow = ((lane >> 4) & 1)*8 + (lane & 7);
    int bcol = ((lane >> 3) & 1) << 3;
    uint32_t boff = (uint32_t)((wn*32 + brow)*MROW + bcol)*2;
    #pragma unroll 1
    for (int ch = 0; ch < 16; ch++) {
        int s = ch & 1;
        cpa_wait<0>();
        __syncthreads();
        if (ch + 1 < 16) { stage(MA_OFF(s^1), Abase, ch+1); stage(MB_OFF(s^1), Bbase, ch+1); cpa_commit(); }
        uint32_t ab = smb + MA_OFF(s) + aoff, bb = smb + MB_OFF(s) + boff;
        #pragma unroll
        for (int kk = 0; kk < 4; kk++) {
            uint32_t A[4][4], B[2][4];
            #pragma unroll
            for (int mi = 0; mi < 4; mi++) ldsm4(A[mi], ab + (uint32_t)(mi*16*MROW + kk*16)*2);
            #pragma unroll
            for (int nb = 0; nb < 2; nb++) ldsm4(B[nb], bb + (uint32_t)(nb*16*MROW + kk*16)*2);
            #pragma unroll
            for (int mi = 0; mi < 4; mi++)
                #pragma unroll
                for (int nb = 0; nb < 2; nb++) {
                    if (ch == 0 && kk == 0) {
                        mma16816z(acc[mi][nb*2+0], A[mi], B[nb][0], B[nb][1]);
                        mma16816z(acc[mi][nb*2+1], A[mi], B[nb][2], B[nb][3]);
                    } else {
                        mma16816(acc[mi][nb*2+0], A[mi], B[nb][0], B[nb][1]);
                        mma16816(acc[mi][nb*2+1], A[mi], B[nb][2], B[nb][3]);
                    }
                }
        }
    }
    size_t pb = (size_t)((bv*4 + tile)*4 + ks)*16384;
    int g2 = lane >> 2, t2 = lane & 3;
    #pragma unroll
    for (int mi = 0; mi < 4; mi++)
        #pragma unroll
        for (int nj = 0; nj < 4; nj++) {
            int r0 = wm*64 + mi*16 + g2, c0 = wn*32 + nj*8 + 2*t2;
            *(float2*)(g_momp + pb + r0*128 + c0)     = make_float2(acc[mi][nj][0], acc[mi][nj][1]);
            *(float2*)(g_momp + pb + (r0+8)*128 + c0) = make_float2(acc[mi][nj][2], acc[mi][nj][3]);
        }
}

// ---------------- K4b: reduce k-split partials -> bf16 Grams ----------------
__global__ void k_gred() {
    int g = blockIdx.x*256 + threadIdx.x;   // 524288 threads, 4 elems each
    #pragma unroll
    for (int r = 0; r < 4; r++) {
        size_t e = (size_t)g + (size_t)r*524288;
        int bv = (int)(e >> 16);
        int i = (int)(e & 65535);
        int dg = i >> 8, kg = i & 255;
        int tile = (dg >> 7)*2 + (kg >> 7);
        size_t base = (size_t)((bv*4 + tile)*4)*16384 + (size_t)(dg & 127)*128 + (kg & 127);
        float s = g_momp[base] + g_momp[base + 16384] + g_momp[base + 32768] + g_momp[base + 49152];
        g_gram[e] = __float2bfloat16(s);
    }
}

// ---------------- K5: quadratic forms qᵀGq ----------------
#define QB_OFF(s) (67584u + (uint32_t)(s)*67584u)
#define SQ_OFF    202752u
#define SMEM_QUAD 204800

__global__ void __launch_bounds__(256, 1) k_quad() {
    extern __shared__ unsigned char sm[];
    uint32_t smb = sptr(sm);
    int qg = blockIdx.x, b = blockIdx.y;
    int head = (qg < 24) ? 0 : ((qg < 26) ? 1 : 2);
    int tid = threadIdx.x, lane = tid & 31, wid = tid >> 5;
    int wm = wid >> 2, wn = wid & 3, g2 = lane >> 2, t2 = lane & 3;
    int vmap[2] = {0, 1 + head};
    load_tile(smb, g_qeff + (size_t)qg*128*DD, tid);
    load_tile(smb + QB_OFF(0), g_gram + (size_t)(b*4 + vmap[0])*65536, tid);
    cpa_commit();
    float qd[2][8];
    #pragma unroll
    for (int v = 0; v < 2; v++)
        #pragma unroll
        for (int i = 0; i < 8; i++) qd[v][i] = 0.f;
    uint32_t aoff = (uint32_t)((wm*64 + (lane & 15))*SROW + ((lane >> 4) << 3))*2;
    int brow = ((lane >> 4) & 1)*8 + (lane & 7);
    int bcol = ((lane >> 3) & 1) << 3;
    uint32_t boff = (uint32_t)((wn*32 + brow)*SROW + bcol)*2;
    const __nv_bfloat16* qa = (const __nv_bfloat16*)sm;
    #pragma unroll 1
    for (int p = 0; p < 4; p++) {
        int s = p & 1, v = p >> 1, kt = p & 1;
        cpa_wait<0>();
        __syncthreads();
        if (p + 1 < 4) {
            int vn = (p+1) >> 1, ktn = (p+1) & 1;
            load_tile(smb + QB_OFF(s^1),
                      g_gram + (size_t)(b*4 + vmap[vn])*65536 + (size_t)(ktn*128)*256, tid);
            cpa_commit();
        }
        float acc[4][4][4];
        uint32_t ab = smb + aoff, bb = smb + QB_OFF(s) + boff;
        #pragma unroll
        for (int kk = 0; kk < 16; kk++) {
            uint32_t A[4][4], B[2][4];
            #pragma unroll
            for (int mi = 0; mi < 4; mi++) ldsm4(A[mi], ab + (uint32_t)(mi*16*SROW + kk*16)*2);
            #pragma unroll
            for (int nb = 0; nb < 2; nb++) ldsm4(B[nb], bb + (uint32_t)(nb*16*SROW + kk*16)*2);
            #pragma unroll
            for (int mi = 0; mi < 4; mi++)
                #pragma unroll
                for (int nb = 0; nb < 2; nb++) {
                    if (kk == 0) {
                        mma16816z(acc[mi][nb*2+0], A[mi], B[nb][0], B[nb][1]);
                        mma16816z(acc[mi][nb*2+1], A[mi], B[nb][2], B[nb][3]);
                    } else {
                        mma16816(acc[mi][nb*2+0], A[mi], B[nb][0], B[nb][1]);
                        mma16816(acc[mi][nb*2+1], A[mi], B[nb][2], B[nb][3]);
                    }
                }
        }
        // weight by q_k (resident qeff tile; conflict-free LDS)
        #pragma unroll
        for (int mi = 0; mi < 4; mi++) {
            int r0 = wm*64 + mi*16 + g2;
            #pragma unroll
            for (int nj = 0; nj < 4; nj++) {
                int k0 = kt*128 + wn*32 + nj*8 + 2*t2;
                float q00 = __bfloat162float(qa[r0*SROW + k0]);
                float q01 = __bfloat162float(qa[r0*SROW + k0 + 1]);
                float q10 = __bfloat162float(qa[(r0+8)*SROW + k0]);
                float q11 = __bfloat162float(qa[(r0+8)*SROW + k0 + 1]);
                qd[v][mi*2+0] += acc[mi][nj][0]*q00 + acc[mi][nj][1]*q01;
                qd[v][mi*2+1] += acc[mi][nj][2]*q10 + acc[mi][nj][3]*q11;
            }
        }
    }
    #pragma unroll
    for (int v = 0; v < 2; v++)
        #pragma unroll
        for (int i = 0; i < 8; i++) {
            qd[v][i] += __shfl_xor_sync(0xffffffffu, qd[v][i], 1);
            qd[v][i] += __shfl_xor_sync(0xffffffffu, qd[v][i], 2);
        }
    float* sq = (float*)(sm + SQ_OFF);   // [4][128]
    for (int v = 0; v < 2; v++) {
        __syncthreads();
        if (t2 == 0) {
            #pragma unroll
            for (int i = 0; i < 8; i++) {
                int row = wm*64 + (i >> 1)*16 + (i & 1)*8 + g2;
                sq[wn*128 + row] = qd[v][i];
            }
        }
        __syncthreads();
        if (tid < 128)
            g_quad[((size_t)b*PQ + qg*128 + tid)*2 + v] =
                sq[tid] + sq[128 + tid] + sq[256 + tid] + sq[384 + tid];
    }
}

// ---------------- K6: assemble + divide + scatter ----------------
__global__ void __launch_bounds__(256) k_fin(float* __restrict__ out) {
    int qg = blockIdx.x, b = blockIdx.y;
    int head = (qg < 24) ? 0 : ((qg < 26) ? 1 : 2);
    int w = threadIdx.x >> 5, lane = threadIdx.x & 31;
    float base = g_base[b][head];
    for (int i = 0; i < 16; i++) {
        int q = w*16 + i;
        int p = qg*128 + q;
        const float* qv = g_qeff32 + (size_t)p*DD;
        float dF = 0.f, dW = 0.f;
        #pragma unroll
        for (int j = 0; j < 2; j++) {
            float4 qq = *(const float4*)(qv + lane*8 + j*4);
            const float* F = g_F1[b] + lane*8 + j*4;
            const float* W = g_Wv1[b][head] + lane*8 + j*4;
            dF += qq.x*F[0] + qq.y*F[1] + qq.z*F[2] + qq.w*F[3];
            dW += qq.x*W[0] + qq.y*W[1] + qq.z*W[2] + qq.w*W[3];
        }
        #pragma unroll
        for (int o = 16; o > 0; o >>= 1) {
            dF += __shfl_xor_sync(0xffffffffu, dF, o);
            dW += __shfl_xor_sync(0xffffffffu, dW, o);
        }
        if (lane == 0) {
            float qm  = g_quad[((size_t)b*PQ + p)*2 + 0];
            float qv2 = g_quad[((size_t)b*PQ + p)*2 + 1];
            float den = 4096.f + dF + 0.5f*qm;
            float num = base + dW + 0.5f*qv2;
            float r = num / den;
            if (p < QT_N)                    out[b*QT_N + p] = r;
            else if (p >= 3072 && p < 3288)  out[NB*QT_N + b*QR_N + (p - 3072)] = r;
            else if (p == 3328)              out[NB*QT_N + NB*QR_N + b] = r;
        }
    }
}

// ---------------- launch ----------------
extern "C" void kernel_launch(void* const* d_in, const int* in_sizes, int n_in,
                              void* d_out, int out_size) {
    const float* feat = (const float*)d_in[0];
    const float* qT  = (const float*)d_in[2];
    const float* WkT = (const float*)d_in[3];
    const float* WvT = (const float*)d_in[4];
    const float* qR  = (const float*)d_in[5];
    const float* WkR = (const float*)d_in[6];
    const float* WvR = (const float*)d_in[7];
    const float* qO  = (const float*)d_in[8];
    const float* WkO = (const float*)d_in[9];
    const float* WvO = (const float*)d_in[10];
    float* out = (float*)d_out;

    const int smemV = 128*260*2 + 3*128*4;
    const int smem3 = 2 * 64 * SROW * (int)sizeof(__nv_bfloat16);
    cudaFuncSetAttribute(k_vsum, cudaFuncAttributeMaxDynamicSharedMemorySize, smemV);
    cudaFuncSetAttribute(k_qeff, cudaFuncAttributeMaxDynamicSharedMemorySize, smem3);
    cudaFuncSetAttribute(k_mom,  cudaFuncAttributeMaxDynamicSharedMemorySize, SMEM_MOM);
    cudaFuncSetAttribute(k_quad, cudaFuncAttributeMaxDynamicSharedMemorySize, SMEM_QUAD);

    k_wv  <<<24, 256>>>(WvT, WvR, WvO);
    k_vsum<<<NPT/128, 256, smemV>>>(feat);
    k_mom1<<<64, 256>>>();
    k_qeff<<<dim3(54, 4), 256, smem3>>>(qT, WkT, qR, WkR, qO, WkO);
    k_mom <<<dim3(4, 4, 32), 256, SMEM_MOM>>>();
    k_gred<<<2048, 256>>>();
    k_quad<<<dim3(27, NB), 256, SMEM_QUAD>>>();
    k_fin <<<dim3(27, NB), 256>>>(out);
}

// round 17
// speedup vs baseline: 1.0102x; 1.0102x over previous
#include <cuda_runtime.h>
#include <cuda_bf16.h>
#include <cstdint>

#define NB 8
#define PTS 4096
#define NPT 32768
#define DD 256
#define QT_N 3000
#define QR_N 216
#define PQ 3456
#define SROW 264
#define MROW 72
#define SCALE 0.0625f

// ---------------- device scratch ----------------
__device__ float          g_wv[3][DD];
__device__ float          g_vsum[3][NPT];
__device__ __nv_bfloat16  g_featTs[(size_t)DD*NPT];    // [d][n] transposed raw feat (16MB)
__device__ __nv_bfloat16  g_qeff[(size_t)PQ*DD];
__device__ float          g_qeff32[(size_t)PQ*DD];
__device__ float          g_F1[NB][DD];
__device__ float          g_Wv1[NB][3][DD];
__device__ float          g_base[NB][3];
__device__ __nv_bfloat16  g_gram[(size_t)32*65536];    // [b*4+var][256][256] bf16
__device__ float          g_quad[(size_t)NB*PQ*2];

struct TileInfo { int head, rowbase, valid; };
__device__ __forceinline__ TileInfo tile_info(int st) {
    TileInfo ti;
    if (st < 48)      { ti.head = 0; ti.rowbase = st*64;      ti.valid = max(0, min(64, QT_N - ti.rowbase)); }
    else if (st < 52) { ti.head = 1; ti.rowbase = (st-48)*64; ti.valid = max(0, min(64, QR_N - ti.rowbase)); }
    else              { ti.head = 2; ti.rowbase = 0;          ti.valid = (st == 52) ? 1 : 0; }
    return ti;
}

// ---------------- helpers ----------------
__device__ __forceinline__ uint32_t sptr(const void* p) {
    return (uint32_t)__cvta_generic_to_shared(p);
}
__device__ __forceinline__ void ldsm4(uint32_t* r, uint32_t a) {
    asm volatile("ldmatrix.sync.aligned.m8n8.x4.shared.b16 {%0,%1,%2,%3},[%4];"
                 : "=r"(r[0]), "=r"(r[1]), "=r"(r[2]), "=r"(r[3]) : "r"(a));
}
__device__ __forceinline__ void mma16816(float* c, const uint32_t* a, uint32_t b0, uint32_t b1) {
    asm volatile("mma.sync.aligned.m16n8k16.row.col.f32.bf16.bf16.f32 "
                 "{%0,%1,%2,%3},{%4,%5,%6,%7},{%8,%9},{%0,%1,%2,%3};"
                 : "+f"(c[0]), "+f"(c[1]), "+f"(c[2]), "+f"(c[3])
                 : "r"(a[0]), "r"(a[1]), "r"(a[2]), "r"(a[3]), "r"(b0), "r"(b1));
}
__device__ __forceinline__ void mma16816z(float* c, const uint32_t* a, uint32_t b0, uint32_t b1) {
    asm volatile("mma.sync.aligned.m16n8k16.row.col.f32.bf16.bf16.f32 "
                 "{%0,%1,%2,%3},{%4,%5,%6,%7},{%8,%9},{%10,%10,%10,%10};"
                 : "=f"(c[0]), "=f"(c[1]), "=f"(c[2]), "=f"(c[3])
                 : "r"(a[0]), "r"(a[1]), "r"(a[2]), "r"(a[3]), "r"(b0), "r"(b1), "f"(0.f));
}
__device__ __forceinline__ void cpa16(uint32_t dst, const void* src) {
    asm volatile("cp.async.cg.shared.global [%0],[%1],16;" :: "r"(dst), "l"(src) : "memory");
}
__device__ __forceinline__ void cpa_commit() { asm volatile("cp.async.commit_group;" ::: "memory"); }
template<int N> __device__ __forceinline__ void cpa_wait() {
    asm volatile("cp.async.wait_group %0;" :: "n"(N) : "memory");
}
// stage 128x256 bf16 tile (gsrc row stride 256) into smem stride SROW
__device__ __forceinline__ void load_tile(uint32_t sdst, const __nv_bfloat16* gsrc, int tid) {
    #pragma unroll
    for (int i = 0; i < 16; i++) {
        int idx = tid + i*256;
        int r = idx >> 5, c = idx & 31;
        cpa16(sdst + (uint32_t)(r*SROW + c*8)*2, gsrc + r*DD + c*8);
    }
}

// ---------------- K1: wv[h][c] = sum_d Wv_h[c][d] ----------------
__global__ void k_wv(const float* __restrict__ WvT, const float* __restrict__ WvR,
                     const float* __restrict__ WvO) {
    int h  = blockIdx.x >> 3;
    int cg = blockIdx.x & 7;
    const float* W = (h == 0) ? WvT : (h == 1) ? WvR : WvO;
    int w = threadIdx.x >> 5, lane = threadIdx.x & 31;
    #pragma unroll
    for (int i = 0; i < 4; i++) {
        int c = cg*32 + w*4 + i;
        const float* row = W + c*DD;
        float s = 0.f;
        #pragma unroll
        for (int j = 0; j < 8; j++) s += row[lane + j*32];
        #pragma unroll
        for (int o = 16; o > 0; o >>= 1) s += __shfl_xor_sync(0xffffffffu, s, o);
        if (lane == 0) g_wv[h][c] = s;
    }
}

// ---------------- K2: v per point + transposed raw bf16 feat ----------------
__global__ void __launch_bounds__(256) k_vsum(const float* __restrict__ feat) {
    extern __shared__ unsigned char svm[];
    __nv_bfloat16* tile = (__nv_bfloat16*)svm;      // [128][260]
    int gbase = blockIdx.x * 128;
    int tid = threadIdx.x, w = tid >> 5, lane = tid & 31;
    int d0 = lane*4;
    for (int it = 0; it < 16; it++) {
        int pt = w*16 + it;
        const float4* row4 = (const float4*)(feat + (size_t)(gbase + pt)*DD);
        float4 a = row4[lane], bq = row4[lane + 32];
        float f[8] = {a.x, a.y, a.z, a.w, bq.x, bq.y, bq.z, bq.w};
        float s0 = 0.f, s1 = 0.f, s2 = 0.f;
        #pragma unroll
        for (int i = 0; i < 4; i++) {
            s0 += f[i]*g_wv[0][d0+i] + f[4+i]*g_wv[0][128+d0+i];
            s1 += f[i]*g_wv[1][d0+i] + f[4+i]*g_wv[1][128+d0+i];
            s2 += f[i]*g_wv[2][d0+i] + f[4+i]*g_wv[2][128+d0+i];
        }
        #pragma unroll
        for (int o = 16; o > 0; o >>= 1) {
            s0 += __shfl_xor_sync(0xffffffffu, s0, o);
            s1 += __shfl_xor_sync(0xffffffffu, s1, o);
            s2 += __shfl_xor_sync(0xffffffffu, s2, o);
        }
        union { uint2 u; __nv_bfloat16 h[4]; } p0, p1;
        #pragma unroll
        for (int i = 0; i < 4; i++) { p0.h[i] = __float2bfloat16(f[i]); p1.h[i] = __float2bfloat16(f[4+i]); }
        *(uint2*)(tile + pt*260 + d0)       = p0.u;
        *(uint2*)(tile + pt*260 + 128 + d0) = p1.u;
        if (lane == 0) {
            g_vsum[0][gbase + pt] = s0; g_vsum[1][gbase + pt] = s1; g_vsum[2][gbase + pt] = s2;
        }
    }
    __syncthreads();
    // phase2: 256 d-rows over 8 warps; coalesced bf16 stores
    for (int row = w; row < 256; row += 8) {
        size_t dst = (size_t)row*NPT + gbase + lane;
        #pragma unroll
        for (int j = 0; j < 4; j++) {
            int p = lane + 32*j;
            g_featTs[dst + 32*j] = tile[p*260 + row];
        }
    }
}

// ---------------- K2b: first moments (exact fp32) ----------------
__global__ void __launch_bounds__(256) k_mom1() {
    int b = blockIdx.x >> 3, dseg = blockIdx.x & 7;
    int w = threadIdx.x >> 5, lane = threadIdx.x & 31;
    #pragma unroll 1
    for (int i = 0; i < 4; i++) {
        int d = dseg*32 + w*4 + i;
        const __nv_bfloat16* fr = g_featTs + (size_t)d*NPT + b*PTS;
        const float* v0 = g_vsum[0] + b*PTS;
        const float* v1 = g_vsum[1] + b*PTS;
        const float* v2 = g_vsum[2] + b*PTS;
        float fs = 0.f, w0 = 0.f, w1 = 0.f, w2 = 0.f;
        for (int c = 0; c < 16; c++) {
            int n0 = lane*8 + c*256;
            uint4 u = *(const uint4*)(fr + n0);
            const __nv_bfloat16* hb = (const __nv_bfloat16*)&u;
            float4 va = *(const float4*)(v0 + n0), vb = *(const float4*)(v0 + n0 + 4);
            float4 wa = *(const float4*)(v1 + n0), wb = *(const float4*)(v1 + n0 + 4);
            float4 xa = *(const float4*)(v2 + n0), xb = *(const float4*)(v2 + n0 + 4);
            float fv[8];
            #pragma unroll
            for (int k = 0; k < 8; k++) { fv[k] = __bfloat162float(hb[k]); fs += fv[k]; }
            w0 += fv[0]*va.x + fv[1]*va.y + fv[2]*va.z + fv[3]*va.w
                + fv[4]*vb.x + fv[5]*vb.y + fv[6]*vb.z + fv[7]*vb.w;
            w1 += fv[0]*wa.x + fv[1]*wa.y + fv[2]*wa.z + fv[3]*wa.w
                + fv[4]*wb.x + fv[5]*wb.y + fv[6]*wb.z + fv[7]*wb.w;
            w2 += fv[0]*xa.x + fv[1]*xa.y + fv[2]*xa.z + fv[3]*xa.w
                + fv[4]*xb.x + fv[5]*xb.y + fv[6]*xb.z + fv[7]*xb.w;
        }
        #pragma unroll
        for (int o = 16; o > 0; o >>= 1) {
            fs += __shfl_xor_sync(0xffffffffu, fs, o);
            w0 += __shfl_xor_sync(0xffffffffu, w0, o);
            w1 += __shfl_xor_sync(0xffffffffu, w1, o);
            w2 += __shfl_xor_sync(0xffffffffu, w2, o);
        }
        if (lane == 0) {
            g_F1[b][d] = fs;
            g_Wv1[b][0][d] = w0; g_Wv1[b][1][d] = w1; g_Wv1[b][2][d] = w2;
        }
    }
    if (dseg == 0 && w < 3) {
        float s = 0.f;
        for (int j = 0; j < 32; j++) {
            float4 v = *(const float4*)(g_vsum[w] + b*PTS + j*128 + lane*4);
            s += v.x + v.y + v.z + v.w;
        }
        #pragma unroll
        for (int o = 16; o > 0; o >>= 1) s += __shfl_xor_sync(0xffffffffu, s, o);
        if (lane == 0) g_base[b][w] = s;
    }
}

// ---------------- K3: Qeff bf16 + fp32 ----------------
__device__ __forceinline__ void gemm64(const __nv_bfloat16* sa, const __nv_bfloat16* sb,
                                       float acc[2][2][4], int wm, int wn, int lane) {
    int arow = lane & 15, acol = (lane >> 4) << 3;
    uint32_t abase0 = sptr(sa + (wm*32 + arow)*SROW + acol);
    uint32_t abase1 = abase0 + 16*SROW*2;
    int brow = ((lane >> 4) & 1)*8 + (lane & 7);
    int bcol = ((lane >> 3) & 1) << 3;
    uint32_t bbase = sptr(sb + (wn*16 + brow)*SROW + bcol);
    #pragma unroll
    for (int k0 = 0; k0 < DD; k0 += 16) {
        uint32_t A0[4], A1[4], Bv[4];
        ldsm4(A0, abase0 + k0*2);
        ldsm4(A1, abase1 + k0*2);
        ldsm4(Bv, bbase  + k0*2);
        mma16816(acc[0][0], A0, Bv[0], Bv[1]);
        mma16816(acc[0][1], A0, Bv[2], Bv[3]);
        mma16816(acc[1][0], A1, Bv[0], Bv[1]);
        mma16816(acc[1][1], A1, Bv[2], Bv[3]);
    }
}

__global__ void __launch_bounds__(256) k_qeff(const float* __restrict__ qTp, const float* __restrict__ WkT,
                                              const float* __restrict__ qRp, const float* __restrict__ WkR,
                                              const float* __restrict__ qOp, const float* __restrict__ WkO) {
    extern __shared__ __nv_bfloat16 sm3[];
    __nv_bfloat16* sa = sm3;
    __nv_bfloat16* sb = sm3 + 64*SROW;
    int st = blockIdx.x, ct = blockIdx.y;
    TileInfo ti = tile_info(st);
    const float* Q  = (ti.head == 0) ? qTp : (ti.head == 1) ? qRp : qOp;
    const float* Wk = (ti.head == 0) ? WkT : (ti.head == 1) ? WkR : WkO;
    int tid = threadIdx.x;
    #pragma unroll 4
    for (int i = tid; i < 64*64; i += 256) {
        int r = i >> 6, c4 = (i & 63) << 2;
        float4 qv = make_float4(0.f, 0.f, 0.f, 0.f);
        if (r < ti.valid) qv = *(const float4*)(Q + (size_t)(ti.rowbase + r)*DD + c4);
        float4 wv = *(const float4*)(Wk + (size_t)(ct*64 + r)*DD + c4);
        union { uint2 u; __nv_bfloat16 b[4]; } pq, pw;
        pq.b[0] = __float2bfloat16(qv.x); pq.b[1] = __float2bfloat16(qv.y);
        pq.b[2] = __float2bfloat16(qv.z); pq.b[3] = __float2bfloat16(qv.w);
        pw.b[0] = __float2bfloat16(wv.x); pw.b[1] = __float2bfloat16(wv.y);
        pw.b[2] = __float2bfloat16(wv.z); pw.b[3] = __float2bfloat16(wv.w);
        *(uint2*)(sa + r*SROW + c4) = pq.u;
        *(uint2*)(sb + r*SROW + c4) = pw.u;
    }
    __syncthreads();
    int lane = tid & 31, w = tid >> 5, wm = w >> 2, wn = w & 3;
    float acc[2][2][4];
    #pragma unroll
    for (int a = 0; a < 2; a++)
        #pragma unroll
        for (int b2 = 0; b2 < 2; b2++)
            #pragma unroll
            for (int c = 0; c < 4; c++) acc[a][b2][c] = 0.f;
    gemm64(sa, sb, acc, wm, wn, lane);
    int g2 = lane >> 2, t = lane & 3;
    #pragma unroll
    for (int mi = 0; mi < 2; mi++)
        #pragma unroll
        for (int nj = 0; nj < 2; nj++) {
            int cc = ct*64 + wn*16 + nj*8 + 2*t;
            int p0 = st*64 + wm*32 + mi*16 + g2;
            float v0 = acc[mi][nj][0]*SCALE, v1 = acc[mi][nj][1]*SCALE;
            float v2 = acc[mi][nj][2]*SCALE, v3 = acc[mi][nj][3]*SCALE;
            __nv_bfloat162 lo, hi;
            lo.x = __float2bfloat16(v0); lo.y = __float2bfloat16(v1);
            hi.x = __float2bfloat16(v2); hi.y = __float2bfloat16(v3);
            *(__nv_bfloat162*)(g_qeff + (size_t)p0*DD + cc)     = lo;
            *(__nv_bfloat162*)(g_qeff + (size_t)(p0+8)*DD + cc) = hi;
            *(float2*)(g_qeff32 + (size_t)p0*DD + cc)     = make_float2(v0, v1);
            *(float2*)(g_qeff32 + (size_t)(p0+8)*DD + cc) = make_float2(v2, v3);
        }
}

// ---------------- K4: Gram tiles, symmetric (jobs: (0,0), (0,1)+T, (1,1)) ----------------
#define MA_OFF(s) ((uint32_t)(s)*18432u)
#define MB_OFF(s) (36864u + (uint32_t)(s)*18432u)
#define MV_OFF(s) (73728u + (uint32_t)(s)*256u)
#define TR_OFF    74240u
#define SMEM_MOM  (74240 + 128*136*2)

__global__ void __launch_bounds__(256, 1) k_mom() {
    extern __shared__ unsigned char sm[];
    uint32_t smb = sptr(sm);
    int job = blockIdx.x, b = blockIdx.y, var = blockIdx.z;
    int dhA = (job == 2) ? 128 : 0;
    int dhB = (job == 0) ? 0 : 128;
    bool twoStage = (job == 1);
    int tid = threadIdx.x, lane = tid & 31, wid = tid >> 5;
    int wm = wid >> 2, wn = wid & 3;
    int nbase = b*PTS;

    auto stageHalf = [&](uint32_t soff, int dh, int ch) {
        #pragma unroll
        for (int t = 0; t < 4; t++) {
            int idx = tid + t*256, r = idx >> 3, c8 = idx & 7;
            cpa16(smb + soff + (uint32_t)(r*MROW + c8*8)*2,
                  g_featTs + (size_t)(dh + r)*NPT + nbase + ch*64 + c8*8);
        }
    };
    auto stageV = [&](uint32_t soff, int ch) {
        if (var > 0 && tid < 16)
            cpa16(smb + soff + (uint32_t)tid*16, g_vsum[var-1] + nbase + ch*64 + tid*4);
    };

    stageHalf(MA_OFF(0), dhA, 0);
    if (twoStage) stageHalf(MB_OFF(0), dhB, 0);
    stageV(MV_OFF(0), 0);
    cpa_commit();

    float acc[4][4][4];
    uint32_t aoff = (uint32_t)((wm*64 + (lane & 15))*MROW + ((lane >> 4) << 3))*2;
    int brow = ((lane >> 4) & 1)*8 + (lane & 7);
    int bcol = ((lane >> 3) & 1) << 3;
    uint32_t boff = (uint32_t)((wn*32 + brow)*MROW + bcol)*2;

    #pragma unroll 1
    for (int ch = 0; ch < 64; ch++) {
        int s = ch & 1;
        cpa_wait<0>();
        __syncthreads();
        if (ch + 1 < 64) {
            stageHalf(MA_OFF(s^1), dhA, ch + 1);
            if (twoStage) stageHalf(MB_OFF(s^1), dhB, ch + 1);
            stageV(MV_OFF(s^1), ch + 1);
            cpa_commit();
        }
        uint32_t Bbase;
        if (var > 0) {
            const float* vv = (const float*)(sm + MV_OFF(s));
            uint32_t srcO = twoStage ? MB_OFF(s) : MA_OFF(s);
            uint32_t dstO = MB_OFF(s);
            #pragma unroll
            for (int t = 0; t < 4; t++) {
                int idx = tid + t*256, r = idx >> 3, c8 = idx & 7;
                uint32_t off = (uint32_t)(r*MROW + c8*8)*2;
                uint4 u = *(uint4*)(sm + srcO + off);
                __nv_bfloat16* h = (__nv_bfloat16*)&u;
                __nv_bfloat16 o[8];
                #pragma unroll
                for (int j = 0; j < 8; j++)
                    o[j] = __float2bfloat16(__bfloat162float(h[j]) * vv[c8*8 + j]);
                *(uint4*)(sm + dstO + off) = *(uint4*)o;
            }
            Bbase = MB_OFF(s);
            __syncthreads();
        } else {
            Bbase = twoStage ? MB_OFF(s) : MA_OFF(s);
        }
        uint32_t ab = smb + MA_OFF(s) + aoff, bb = smb + Bbase + boff;
        #pragma unroll
        for (int kk = 0; kk < 4; kk++) {
            uint32_t A[4][4], B[2][4];
            #pragma unroll
            for (int mi = 0; mi < 4; mi++) ldsm4(A[mi], ab + (uint32_t)(mi*16*MROW + kk*16)*2);
            #pragma unroll
            for (int nb = 0; nb < 2; nb++) ldsm4(B[nb], bb + (uint32_t)(nb*16*MROW + kk*16)*2);
            #pragma unroll
            for (int mi = 0; mi < 4; mi++)
                #pragma unroll
                for (int nb = 0; nb < 2; nb++) {
                    if (ch == 0 && kk == 0) {
                        mma16816z(acc[mi][nb*2+0], A[mi], B[nb][0], B[nb][1]);
                        mma16816z(acc[mi][nb*2+1], A[mi], B[nb][2], B[nb][3]);
                    } else {
                        mma16816(acc[mi][nb*2+0], A[mi], B[nb][0], B[nb][1]);
                        mma16816(acc[mi][nb*2+1], A[mi], B[nb][2], B[nb][3]);
                    }
                }
        }
    }

    int g2 = lane >> 2, t2 = lane & 3;
    size_t gb = (size_t)(b*4 + var)*65536;
    #pragma unroll
    for (int mi = 0; mi < 4; mi++)
        #pragma unroll
        for (int nj = 0; nj < 4; nj++) {
            int r0 = dhA + wm*64 + mi*16 + g2, c0 = dhB + wn*32 + nj*8 + 2*t2;
            __nv_bfloat162 p01, p23;
            p01.x = __float2bfloat16(acc[mi][nj][0]); p01.y = __float2bfloat16(acc[mi][nj][1]);
            p23.x = __float2bfloat16(acc[mi][nj][2]); p23.y = __float2bfloat16(acc[mi][nj][3]);
            *(__nv_bfloat162*)(g_gram + gb + (size_t)r0*256 + c0)     = p01;
            *(__nv_bfloat162*)(g_gram + gb + (size_t)(r0+8)*256 + c0) = p23;
        }
    if (job == 1) {
        // also write transposed tile (1,0)
        __nv_bfloat16* tr = (__nv_bfloat16*)(sm + TR_OFF);
        __syncthreads();
        #pragma unroll
        for (int mi = 0; mi < 4; mi++)
            #pragma unroll
            for (int nj = 0; nj < 4; nj++) {
                int r0 = wm*64 + mi*16 + g2, c0 = wn*32 + nj*8 + 2*t2;
                tr[r0*136 + c0]     = __float2bfloat16(acc[mi][nj][0]);
                tr[r0*136 + c0 + 1] = __float2bfloat16(acc[mi][nj][1]);
                tr[(r0+8)*136 + c0]     = __float2bfloat16(acc[mi][nj][2]);
                tr[(r0+8)*136 + c0 + 1] = __float2bfloat16(acc[mi][nj][3]);
            }
        __syncthreads();
        int kr = tid >> 1, chh = tid & 1;
        #pragma unroll
        for (int g8 = 0; g8 < 8; g8++) {
            __nv_bfloat16 tmp[8];
            #pragma unroll
            for (int j = 0; j < 8; j++)
                tmp[j] = tr[(chh*64 + g8*8 + j)*136 + kr];
            *(uint4*)(g_gram + gb + (size_t)(128 + kr)*256 + chh*64 + g8*8) = *(uint4*)tmp;
        }
    }
}

// ---------------- K5: quadratic forms qᵀGq ----------------
#define QB_OFF(s) (67584u + (uint32_t)(s)*67584u)
#define SQ_OFF    202752u
#define SMEM_QUAD 204800

__global__ void __launch_bounds__(256, 1) k_quad() {
    extern __shared__ unsigned char sm[];
    uint32_t smb = sptr(sm);
    int qg = blockIdx.x, b = blockIdx.y;
    int head = (qg < 24) ? 0 : ((qg < 26) ? 1 : 2);
    int tid = threadIdx.x, lane = tid & 31, wid = tid >> 5;
    int wm = wid >> 2, wn = wid & 3, g2 = lane >> 2, t2 = lane & 3;
    int vmap[2] = {0, 1 + head};
    load_tile(smb, g_qeff + (size_t)qg*128*DD, tid);
    load_tile(smb + QB_OFF(0), g_gram + (size_t)(b*4 + vmap[0])*65536, tid);
    cpa_commit();
    float qd[2][8];
    #pragma unroll
    for (int v = 0; v < 2; v++)
        #pragma unroll
        for (int i = 0; i < 8; i++) qd[v][i] = 0.f;
    uint32_t aoff = (uint32_t)((wm*64 + (lane & 15))*SROW + ((lane >> 4) << 3))*2;
    int brow = ((lane >> 4) & 1)*8 + (lane & 7);
    int bcol = ((lane >> 3) & 1) << 3;
    uint32_t boff = (uint32_t)((wn*32 + brow)*SROW + bcol)*2;
    const __nv_bfloat16* qa = (const __nv_bfloat16*)sm;
    #pragma unroll 1
    for (int p = 0; p < 4; p++) {
        int s = p & 1, v = p >> 1, kt = p & 1;
        cpa_wait<0>();
        __syncthreads();
        if (p + 1 < 4) {
            int vn = (p+1) >> 1, ktn = (p+1) & 1;
            load_tile(smb + QB_OFF(s^1),
                      g_gram + (size_t)(b*4 + vmap[vn])*65536 + (size_t)(ktn*128)*256, tid);
            cpa_commit();
        }
        float acc[4][4][4];
        uint32_t ab = smb + aoff, bb = smb + QB_OFF(s) + boff;
        #pragma unroll
        for (int kk = 0; kk < 16; kk++) {
            uint32_t A[4][4], B[2][4];
            #pragma unroll
            for (int mi = 0; mi < 4; mi++) ldsm4(A[mi], ab + (uint32_t)(mi*16*SROW + kk*16)*2);
            #pragma unroll
            for (int nb = 0; nb < 2; nb++) ldsm4(B[nb], bb + (uint32_t)(nb*16*SROW + kk*16)*2);
            #pragma unroll
            for (int mi = 0; mi < 4; mi++)
                #pragma unroll
                for (int nb = 0; nb < 2; nb++) {
                    if (kk == 0) {
                        mma16816z(acc[mi][nb*2+0], A[mi], B[nb][0], B[nb][1]);
                        mma16816z(acc[mi][nb*2+1], A[mi], B[nb][2], B[nb][3]);
                    } else {
                        mma16816(acc[mi][nb*2+0], A[mi], B[nb][0], B[nb][1]);
                        mma16816(acc[mi][nb*2+1], A[mi], B[nb][2], B[nb][3]);
                    }
                }
        }
        #pragma unroll
        for (int mi = 0; mi < 4; mi++) {
            int r0 = wm*64 + mi*16 + g2;
            #pragma unroll
            for (int nj = 0; nj < 4; nj++) {
                int k0 = kt*128 + wn*32 + nj*8 + 2*t2;
                float q00 = __bfloat162float(qa[r0*SROW + k0]);
                float q01 = __bfloat162float(qa[r0*SROW + k0 + 1]);
                float q10 = __bfloat162float(qa[(r0+8)*SROW + k0]);
                float q11 = __bfloat162float(qa[(r0+8)*SROW + k0 + 1]);
                qd[v][mi*2+0] += acc[mi][nj][0]*q00 + acc[mi][nj][1]*q01;
                qd[v][mi*2+1] += acc[mi][nj][2]*q10 + acc[mi][nj][3]*q11;
            }
        }
    }
    #pragma unroll
    for (int v = 0; v < 2; v++)
        #pragma unroll
        for (int i = 0; i < 8; i++) {
            qd[v][i] += __shfl_xor_sync(0xffffffffu, qd[v][i], 1);
            qd[v][i] += __shfl_xor_sync(0xffffffffu, qd[v][i], 2);
        }
    float* sq = (float*)(sm + SQ_OFF);   // [4][128]
    for (int v = 0; v < 2; v++) {
        __syncthreads();
        if (t2 == 0) {
            #pragma unroll
            for (int i = 0; i < 8; i++) {
                int row = wm*64 + (i >> 1)*16 + (i & 1)*8 + g2;
                sq[wn*128 + row] = qd[v][i];
            }
        }
        __syncthreads();
        if (tid < 128)
            g_quad[((size_t)b*PQ + qg*128 + tid)*2 + v] =
                sq[tid] + sq[128 + tid] + sq[256 + tid] + sq[384 + tid];
    }
}

// ---------------- K6: assemble + divide + scatter ----------------
__global__ void __launch_bounds__(256) k_fin(float* __restrict__ out) {
    int qg = blockIdx.x, b = blockIdx.y;
    int head = (qg < 24) ? 0 : ((qg < 26) ? 1 : 2);
    int w = threadIdx.x >> 5, lane = threadIdx.x & 31;
    float base = g_base[b][head];
    for (int i = 0; i < 16; i++) {
        int q = w*16 + i;
        int p = qg*128 + q;
        const float* qv = g_qeff32 + (size_t)p*DD;
        float dF = 0.f, dW = 0.f;
        #pragma unroll
        for (int j = 0; j < 2; j++) {
            float4 qq = *(const float4*)(qv + lane*8 + j*4);
            const float* F = g_F1[b] + lane*8 + j*4;
            const float* W = g_Wv1[b][head] + lane*8 + j*4;
            dF += qq.x*F[0] + qq.y*F[1] + qq.z*F[2] + qq.w*F[3];
            dW += qq.x*W[0] + qq.y*W[1] + qq.z*W[2] + qq.w*W[3];
        }
        #pragma unroll
        for (int o = 16; o > 0; o >>= 1) {
            dF += __shfl_xor_sync(0xffffffffu, dF, o);
            dW += __shfl_xor_sync(0xffffffffu, dW, o);
        }
        if (lane == 0) {
            float qm  = g_quad[((size_t)b*PQ + p)*2 + 0];
            float qv2 = g_quad[((size_t)b*PQ + p)*2 + 1];
            float den = 4096.f + dF + 0.5f*qm;
            float num = base + dW + 0.5f*qv2;
            float r = num / den;
            if (p < QT_N)                    out[b*QT_N + p] = r;
            else if (p >= 3072 && p < 3288)  out[NB*QT_N + b*QR_N + (p - 3072)] = r;
            else if (p == 3328)              out[NB*QT_N + NB*QR_N + b] = r;
        }
    }
}

// ---------------- launch ----------------
extern "C" void kernel_launch(void* const* d_in, const int* in_sizes, int n_in,
                              void* d_out, int out_size) {
    const float* feat = (const float*)d_in[0];
    const float* qT  = (const float*)d_in[2];
    const float* WkT = (const float*)d_in[3];
    const float* WvT = (const float*)d_in[4];
    const float* qR  = (const float*)d_in[5];
    const float* WkR = (const float*)d_in[6];
    const float* WvR = (const float*)d_in[7];
    const float* qO  = (const float*)d_in[8];
    const float* WkO = (const float*)d_in[9];
    const float* WvO = (const float*)d_in[10];
    float* out = (float*)d_out;

    const int smemV = 128*260*2;
    const int smem3 = 2 * 64 * SROW * (int)sizeof(__nv_bfloat16);
    cudaFuncSetAttribute(k_vsum, cudaFuncAttributeMaxDynamicSharedMemorySize, smemV);
    cudaFuncSetAttribute(k_qeff, cudaFuncAttributeMaxDynamicSharedMemorySize, smem3);
    cudaFuncSetAttribute(k_mom,  cudaFuncAttributeMaxDynamicSharedMemorySize, SMEM_MOM);
    cudaFuncSetAttribute(k_quad, cudaFuncAttributeMaxDynamicSharedMemorySize, SMEM_QUAD);

    k_wv  <<<24, 256>>>(WvT, WvR, WvO);
    k_vsum<<<NPT/128, 256, smemV>>>(feat);
    k_mom1<<<64, 256>>>();
    k_qeff<<<dim3(54, 4), 256, smem3>>>(qT, WkT, qR, WkR, qO, WkO);
    k_mom <<<dim3(3, NB, 4), 256, SMEM_MOM>>>();
    k_quad<<<dim3(27, NB), 256, SMEM_QUAD>>>();
    k_fin <<<dim3(27, NB), 256>>>(out);
}